// round 8
// baseline (speedup 1.0000x reference)
#include <cuda_runtime.h>
#include <cstdint>

// FSMN depthwise strided FIR on GB300 — R8.
// Base = R5 (79.9us best). Single change to the compute stream: window ring
// is 16 deep (power-of-2 -> static &15 indexing, unlike R7's %10 which hit
// the 128-reg cap) and each refill is issued 8 tap-iterations ahead of its
// first use: 8 iter x 8 FFMA2 x 2 cyc = 128 issue-cycles of cover vs 29-cyc
// LDS latency. Same LDS traffic as R5, reorganized. One parity at a time
// (acc[8]) + depth-4 tap prefetch keeps regs ~95.
//
// out[b,t,d] = sum_{i=0..19} filt[i,d]*x[b,t-(20-i)*2,d]
//            + filt[20,d]*x[b,t,d]
//            + sum_{j=0..19} filt[21+j,d]*x[b,t+1+2j,d],  zero-padded.

#define B_   32
#define T_   2000
#define DPAL 256        // d-pairs across all of D
#define DPB  32         // d-pairs per block
#define RT   8          // outputs per parity chunk
#define TT   128        // t-outputs per tile
#define TPB  4          // tiles per block; grid.x=4 -> 16 tiles
#define ROWS (TT + 80)  // 208 smem rows per tile
#define STRIDE (ROWS * DPB)            // u64 per buffer
#define SMEM_BYTES (2 * STRIDE * 8)    // 106496 B

__device__ __forceinline__ uint64_t f2fma(uint64_t a, uint64_t b, uint64_t c) {
    uint64_t r;
    asm("fma.rn.f32x2 %0, %1, %2, %3;" : "=l"(r) : "l"(a), "l"(b), "l"(c));
    return r;
}

__device__ __forceinline__ uint32_t smem_u32(const void* p) {
    uint32_t a;
    asm("{ .reg .u64 t; cvta.to.shared.u64 t, %1; cvt.u32.u64 %0, t; }"
        : "=r"(a) : "l"(p));
    return a;
}

// One dense stream: NT taps over smem rows rb+2l (l = 0..NT+6), taps at
// ftb[c*DPAL]. 16-deep ring, refill distance 8 iterations.
//   iter c uses rows c..c+7 (slots (c+r)&15);
//   refill at iter c writes row c+15 into slot (c+15)&15 (old row c-1,
//   last read at iter c-1); first read of row c+15 is at iter c+8.
template<int NT>
__device__ __forceinline__ void stream_acc(uint64_t* __restrict__ acc,
                                           const uint64_t* __restrict__ sxp,
                                           int rb,
                                           const uint64_t* __restrict__ ftb)
{
    uint64_t tp[4];
#pragma unroll
    for (int k = 0; k < 4; ++k) tp[k] = ftb[(size_t)k * DPAL];

    uint64_t w[16];
#pragma unroll
    for (int l = 0; l < 16; ++l) w[l] = sxp[(rb + 2 * l) * DPB];

#pragma unroll
    for (int c = 0; c < NT; ++c) {
        if (c >= 1 && c + 15 <= NT + 6)          // rows 16 .. NT+6
            w[(c + 15) & 15] = sxp[(rb + 2 * (c + 15)) * DPB];
        const uint64_t tap = tp[c & 3];
        if (c + 4 < NT) tp[c & 3] = ftb[(size_t)(c + 4) * DPAL];
#pragma unroll
        for (int r = 0; r < RT; ++r)
            acc[r] = f2fma(tap, w[(c + r) & 15], acc[r]);
    }
}

__global__ __launch_bounds__(256, 2)
void fsmn_kernel(const float* __restrict__ x,
                 const float* __restrict__ filt,
                 float* __restrict__ out)
{
    extern __shared__ uint64_t sx[];   // [2][ROWS][DPB]

    const int tid = threadIdx.x;
    const int q0  = blockIdx.x * TPB;         // first tile index
    const int dpg = blockIdx.y * DPB;         // d-pair base
    const int b   = blockIdx.z;

    const uint64_t* __restrict__ xg =
        reinterpret_cast<const uint64_t*>(x) + (size_t)b * T_ * DPAL + dpg;
    uint64_t* __restrict__ og =
        reinterpret_cast<uint64_t*>(out) + (size_t)b * T_ * DPAL + dpg;

    const uint32_t sbase = smem_u32(sx);

    // -------- cp.async tile prefetch: 3328 16B units, 13 per thread --------
    auto prefetch = [&](int buf, int qt) {
        const int tb = qt * TT;
        const uint32_t db = sbase + (uint32_t)buf * (STRIDE * 8);
#pragma unroll
        for (int k = 0; k < 13; ++k) {
            const int u   = tid + k * 256;
            const int row = u >> 4;
            const int c16 = u & 15;
            const int t   = tb - 40 + row;
            const char* gp = reinterpret_cast<const char*>(xg + (size_t)t * DPAL)
                             + c16 * 16;
            const uint32_t dst = db + (uint32_t)(row * DPB) * 8 + c16 * 16;
            const int ok = (t >= 0 && t < T_) ? 16 : 0;
            asm volatile("cp.async.cg.shared.global [%0], [%1], 16, %2;"
                         :: "r"(dst), "l"(gp), "r"(ok) : "memory");
        }
        asm volatile("cp.async.commit_group;" ::: "memory");
    };

    const int dpl = tid & (DPB - 1);          // 0..31
    const int g   = tid >> 5;                 // 0..7 (16 t each)
    const uint64_t* __restrict__ fdp =
        reinterpret_cast<const uint64_t*>(filt) + dpg + dpl;

    prefetch(0, q0);

#pragma unroll
    for (int i = 0; i < TPB; ++i) {
        if (i < TPB - 1) {
            prefetch((i + 1) & 1, q0 + i + 1);
            asm volatile("cp.async.wait_group 1;" ::: "memory");
        } else {
            asm volatile("cp.async.wait_group 0;" ::: "memory");
        }
        __syncthreads();

        const int tb = (q0 + i) * TT;
        const uint64_t* __restrict__ sxp = sx + (i & 1) * STRIDE + dpl;

#pragma unroll
        for (int par = 0; par < 2; ++par) {
            const int rb = g * 16 + par;       // smem row of x[t0-40]

            uint64_t acc[RT];
#pragma unroll
            for (int r = 0; r < RT; ++r) acc[r] = 0ull;

            // A stream: left+center taps filt[0..20] over x[t0-40+2l]
            stream_acc<21>(acc, sxp, rb, fdp);
            // B stream: right taps filt[21..40] over x[t0+1+2l]
            stream_acc<20>(acc, sxp, rb + 41, fdp + (size_t)21 * DPAL);

            // store 8 outputs (guard: last tile reaches t=2047)
            const int t0 = tb + g * 16 + par;
#pragma unroll
            for (int r = 0; r < RT; ++r) {
                const int t = t0 + 2 * r;
                if (t < T_) og[(size_t)t * DPAL + dpl] = acc[r];
            }
        }
        __syncthreads();   // protect buf[i&1] before next prefetch
    }
}

extern "C" void kernel_launch(void* const* d_in, const int* in_sizes, int n_in,
                              void* d_out, int out_size)
{
    const float* x    = (const float*)d_in[0];   // [32, 2000, 512] f32
    const float* filt = (const float*)d_in[1];   // [41, 512] f32
    float* out        = (float*)d_out;           // [32, 2000, 512] f32

    cudaFuncSetAttribute(fsmn_kernel,
                         cudaFuncAttributeMaxDynamicSharedMemorySize,
                         SMEM_BYTES);

    dim3 grid(4,            // 4 groups x TPB=4 tiles -> 16 t-tiles
              DPAL / DPB,   // 8 d-pair slabs
              B_);          // 32 batch
    fsmn_kernel<<<grid, 256, SMEM_BYTES>>>(x, filt, out);
}

// round 9
// speedup vs baseline: 1.0147x; 1.0147x over previous
#include <cuda_runtime.h>
#include <cstdint>

// FSMN depthwise strided FIR on GB300 — R9.
// vs R5 (79.9us): trade fat-thread ILP for WARP COUNT. One parity per thread
// (acc[8]+w[8]+tap pipe ~ 38 u64-regs -> ~55 regs), taps staged in SMEM once
// per block (no 42-reg tap arrays), 512-thread blocks, single-buffered tile.
// 2 blocks x 512 = 32 warps/SM = 8 warps/SMSP (was 4): LDS latency and
// fill/sync phases hidden by sibling warps instead of register pipelines
// (which rounds 6-8 proved unaffordable at 128 regs).
//
// out[b,t,d] = sum_{i=0..19} filt[i,d]*x[b,t-(20-i)*2,d]
//            + filt[20,d]*x[b,t,d]
//            + sum_{j=0..19} filt[21+j,d]*x[b,t+1+2j,d],  zero-padded.

#define B_   32
#define T_   2000
#define DPAL 256        // d-pairs across all of D
#define DPB  32         // d-pairs per block
#define RT   8          // outputs per thread (one parity)
#define TT   128        // t-outputs per tile
#define TPB  4          // tiles per block; grid.x=4 -> 16 tiles
#define ROWS (TT + 80)  // 208 smem rows per tile
#define XWORDS (ROWS * DPB)            // 6656 u64
#define FWORDS (41 * DPB)              // 1312 u64
#define SMEM_BYTES ((XWORDS + FWORDS) * 8)   // 63744 B
#define CHUNKS (ROWS * 16)             // 3328 16B units per tile

__device__ __forceinline__ uint64_t f2fma(uint64_t a, uint64_t b, uint64_t c) {
    uint64_t r;
    asm("fma.rn.f32x2 %0, %1, %2, %3;" : "=l"(r) : "l"(a), "l"(b), "l"(c));
    return r;
}

__device__ __forceinline__ uint32_t smem_u32(const void* p) {
    uint32_t a;
    asm("{ .reg .u64 t; cvta.to.shared.u64 t, %1; cvt.u32.u64 %0, t; }"
        : "=r"(a) : "l"(p));
    return a;
}

// One dense stream: NT taps over smem rows rb+2l, taps from smem at
// sft[c*DPB]. 8-deep rotating window (R5-proven), depth-2 tap pipeline.
template<int NT>
__device__ __forceinline__ void stream_acc(uint64_t* __restrict__ acc,
                                           const uint64_t* __restrict__ sxp,
                                           int rb,
                                           const uint64_t* __restrict__ sft)
{
    uint64_t tp[2];
    tp[0] = sft[0];
    tp[1] = sft[DPB];

    uint64_t w[RT];
#pragma unroll
    for (int u = 0; u < RT; ++u)
        w[u] = sxp[(rb + 2 * u) * DPB];

#pragma unroll
    for (int c = 0; c < NT; ++c) {
        const uint64_t tap = tp[c & 1];
        if (c + 2 < NT) tp[c & 1] = sft[(c + 2) * DPB];
#pragma unroll
        for (int r = 0; r < RT; ++r)
            acc[r] = f2fma(tap, w[(c + r) & (RT - 1)], acc[r]);
        if (c + RT <= NT + 6)
            w[c & (RT - 1)] = sxp[(rb + 2 * (c + RT)) * DPB];
    }
}

__global__ __launch_bounds__(512, 2)
void fsmn_kernel(const float* __restrict__ x,
                 const float* __restrict__ filt,
                 float* __restrict__ out)
{
    extern __shared__ uint64_t sm[];   // [XWORDS] x-tile | [FWORDS] filt
    uint64_t* const sx = sm;
    uint64_t* const sf = sm + XWORDS;

    const int tid = threadIdx.x;
    const int q0  = blockIdx.x * TPB;         // first tile index
    const int dpg = blockIdx.y * DPB;         // d-pair base
    const int b   = blockIdx.z;

    const uint64_t* __restrict__ xg =
        reinterpret_cast<const uint64_t*>(x) + (size_t)b * T_ * DPAL + dpg;
    uint64_t* __restrict__ og =
        reinterpret_cast<uint64_t*>(out) + (size_t)b * T_ * DPAL + dpg;
    const uint64_t* __restrict__ fg =
        reinterpret_cast<const uint64_t*>(filt) + dpg;

    // ---- stage filter slab into smem once per block: sf[k*DPB + dpl] ----
#pragma unroll
    for (int k = 0; k < 3; ++k) {
        const int i = tid + k * 512;
        if (i < FWORDS)
            sf[i] = fg[(size_t)(i >> 5) * DPAL + (i & (DPB - 1))];
    }

    const uint32_t sbase = smem_u32(sx);

    const int dpl = tid & (DPB - 1);          // 0..31
    const int par = (tid >> 5) & 1;           // parity owned by this thread
    const int g   = tid >> 6;                 // 0..7 (16 t each)

    const uint64_t* __restrict__ sfp = sf + dpl;

#pragma unroll
    for (int i = 0; i < TPB; ++i) {
        const int tb = (q0 + i) * TT;

        // ---- fill x tile via cp.async (zero-filled pad rows) ----
#pragma unroll
        for (int k = 0; k < 7; ++k) {
            const int u = tid + k * 512;
            if (u < CHUNKS) {
                const int row = u >> 4;
                const int c16 = u & 15;
                const int t   = tb - 40 + row;
                const char* gp =
                    reinterpret_cast<const char*>(xg + (size_t)t * DPAL)
                    + c16 * 16;
                const uint32_t dst = sbase + (uint32_t)(row * DPB) * 8
                                     + c16 * 16;
                const int ok = (t >= 0 && t < T_) ? 16 : 0;
                asm volatile("cp.async.cg.shared.global [%0], [%1], 16, %2;"
                             :: "r"(dst), "l"(gp), "r"(ok) : "memory");
            }
        }
        asm volatile("cp.async.commit_group;" ::: "memory");
        asm volatile("cp.async.wait_group 0;" ::: "memory");
        __syncthreads();

        // ---- compute: 8 outputs of one parity ----
        const uint64_t* __restrict__ sxp = sx + dpl;
        const int rb = g * 16 + par;           // smem row of x[t0-40]

        uint64_t acc[RT];
#pragma unroll
        for (int r = 0; r < RT; ++r) acc[r] = 0ull;

        // A stream: left+center taps filt[0..20] over x[t0-40+2l]
        stream_acc<21>(acc, sxp, rb, sfp);
        // B stream: right taps filt[21..40] over x[t0+1+2l]
        stream_acc<20>(acc, sxp, rb + 41, sfp + 21 * DPB);

        // ---- store 8 outputs (guard: last tile reaches t=2047) ----
        const int t0 = tb + g * 16 + par;
#pragma unroll
        for (int r = 0; r < RT; ++r) {
            const int t = t0 + 2 * r;
            if (t < T_) og[(size_t)t * DPAL + dpl] = acc[r];
        }
        __syncthreads();   // protect sx before next tile's fill
    }
}

extern "C" void kernel_launch(void* const* d_in, const int* in_sizes, int n_in,
                              void* d_out, int out_size)
{
    const float* x    = (const float*)d_in[0];   // [32, 2000, 512] f32
    const float* filt = (const float*)d_in[1];   // [41, 512] f32
    float* out        = (float*)d_out;           // [32, 2000, 512] f32

    cudaFuncSetAttribute(fsmn_kernel,
                         cudaFuncAttributeMaxDynamicSharedMemorySize,
                         SMEM_BYTES);

    dim3 grid(4,            // 4 groups x TPB=4 tiles -> 16 t-tiles
              DPAL / DPB,   // 8 d-pair slabs
              B_);          // 32 batch
    fsmn_kernel<<<grid, 512, SMEM_BYTES>>>(x, filt, out);
}